// round 1
// baseline (speedup 1.0000x reference)
#include <cuda_runtime.h>
#include <cuda_bf16.h>

// out = X @ K where X is (N, 64) = inputs flattened row-major, K = C (x) C.
// Separable form: 2 passes of 8x8 transforms, 1024 FMA per strip instead of 4096.

__global__ __launch_bounds__(128)
void dct_separable_kernel(const float* __restrict__ in,
                          const float* __restrict__ Kmat,
                          float* __restrict__ out,
                          int nstrips)
{
    int strip = blockIdx.x * blockDim.x + threadIdx.x;
    if (strip >= nstrips) return;

    // Recover the 8x8 DCT matrix C from K: K[v, j] = C[0,0]*C[v,j], C[0,0]=sqrt(1/8)
    // => C[v,j] = K[v*64 + j] * sqrt(8)
    float C[64];
#pragma unroll
    for (int idx = 0; idx < 64; ++idx) {
        int v = idx >> 3, j = idx & 7;
        C[idx] = __ldg(&Kmat[v * 64 + j]) * 2.8284271247461903f;
    }

    // Load 64 contiguous floats (one strip) as 16x float4 — batched for MLP.
    float x[64];
    const float4* in4 = reinterpret_cast<const float4*>(in) + (size_t)strip * 16;
#pragma unroll
    for (int k = 0; k < 16; ++k) {
        float4 v = in4[k];
        x[k * 4 + 0] = v.x;
        x[k * 4 + 1] = v.y;
        x[k * 4 + 2] = v.z;
        x[k * 4 + 3] = v.w;
    }

    // Stage 1 (in place): y[u*8+j] = sum_v x[u*8+v] * C[v*8+j]
#pragma unroll
    for (int u = 0; u < 8; ++u) {
        float t[8];
#pragma unroll
        for (int j = 0; j < 8; ++j) {
            float a = x[u * 8 + 0] * C[0 * 8 + j];
#pragma unroll
            for (int v = 1; v < 8; ++v)
                a = fmaf(x[u * 8 + v], C[v * 8 + j], a);
            t[j] = a;
        }
#pragma unroll
        for (int j = 0; j < 8; ++j) x[u * 8 + j] = t[j];
    }

    // Stage 2: out[i*8+j] = sum_u y[u*8+j] * C[u*8+i], streamed out per i-row.
    float4* out4 = reinterpret_cast<float4*>(out) + (size_t)strip * 16;
#pragma unroll
    for (int i = 0; i < 8; ++i) {
        float o[8];
#pragma unroll
        for (int j = 0; j < 8; ++j) {
            float a = x[0 * 8 + j] * C[0 * 8 + i];
#pragma unroll
            for (int u = 1; u < 8; ++u)
                a = fmaf(x[u * 8 + j], C[u * 8 + i], a);
            o[j] = a;
        }
        out4[i * 2 + 0] = make_float4(o[0], o[1], o[2], o[3]);
        out4[i * 2 + 1] = make_float4(o[4], o[5], o[6], o[7]);
    }
}

extern "C" void kernel_launch(void* const* d_in, const int* in_sizes, int n_in,
                              void* d_out, int out_size)
{
    const float* in   = (const float*)d_in[0];   // (8,3,1024,1024) fp32
    const float* Kmat = (const float*)d_in[1];   // (64,64) fp32
    float* out        = (float*)d_out;           // same shape as input

    int nstrips = in_sizes[0] / 64;              // 393216
    int threads = 128;
    int blocks  = (nstrips + threads - 1) / threads;
    dct_separable_kernel<<<blocks, threads>>>(in, Kmat, out, nstrips);
}

// round 2
// speedup vs baseline: 2.3634x; 2.3634x over previous
#include <cuda_runtime.h>

// DCT-per-8x8-patch == out(N,64) = X(N,64) @ (C ⊗ C).
// Separable: two 8-point passes, 1024 FMA/strip, all coefficients as FFMA
// immediates. Gmem fully coalesced via padded smem staging.

#define THREADS 128
#define STRIDE4 17   // float4 stride per strip in smem (pad: bank-conflict-free)

// CT[v][j] = s(v) * cos((2j+1) v pi / 16); stage1 multiplies CT[v][j], stage2 CT[u][i].
#define DCT_TABLE(CT)                                                                  \
    const float CT[8][8] = {                                                           \
        {0.353553391f, 0.353553391f, 0.353553391f, 0.353553391f,                       \
         0.353553391f, 0.353553391f, 0.353553391f, 0.353553391f},                      \
        {0.490392640f, 0.415734806f, 0.277785117f, 0.097545161f,                       \
         -0.097545161f, -0.277785117f, -0.415734806f, -0.490392640f},                  \
        {0.461939766f, 0.191341716f, -0.191341716f, -0.461939766f,                     \
         -0.461939766f, -0.191341716f, 0.191341716f, 0.461939766f},                    \
        {0.415734806f, -0.097545161f, -0.490392640f, -0.277785117f,                    \
         0.277785117f, 0.490392640f, 0.097545161f, -0.415734806f},                     \
        {0.353553391f, -0.353553391f, -0.353553391f, 0.353553391f,                     \
         0.353553391f, -0.353553391f, -0.353553391f, 0.353553391f},                    \
        {0.277785117f, -0.490392640f, 0.097545161f, 0.415734806f,                      \
         -0.415734806f, -0.097545161f, 0.490392640f, -0.277785117f},                   \
        {0.191341716f, -0.461939766f, 0.461939766f, -0.191341716f,                     \
         -0.191341716f, 0.461939766f, -0.461939766f, 0.191341716f},                    \
        {0.097545161f, -0.277785117f, 0.415734806f, -0.490392640f,                     \
         0.490392640f, -0.415734806f, 0.277785117f, -0.097545161f}};

__device__ __forceinline__ void dct64_inplace(float x[64])
{
    DCT_TABLE(CT);
    // Stage 1: y[u*8+j] = sum_v x[u*8+v] * CT[v][j]
#pragma unroll
    for (int u = 0; u < 8; ++u) {
        float t[8];
#pragma unroll
        for (int j = 0; j < 8; ++j) {
            float a = x[u * 8 + 0] * CT[0][j];
#pragma unroll
            for (int v = 1; v < 8; ++v) a = fmaf(x[u * 8 + v], CT[v][j], a);
            t[j] = a;
        }
#pragma unroll
        for (int j = 0; j < 8; ++j) x[u * 8 + j] = t[j];
    }
    // Stage 2: out[i*8+j] = sum_u y[u*8+j] * CT[u][i]
    float y[64];
#pragma unroll
    for (int k = 0; k < 64; ++k) y[k] = x[k];
#pragma unroll
    for (int i = 0; i < 8; ++i) {
#pragma unroll
        for (int j = 0; j < 8; ++j) {
            float a = y[0 * 8 + j] * CT[0][i];
#pragma unroll
            for (int u = 1; u < 8; ++u) a = fmaf(y[u * 8 + j], CT[u][i], a);
            x[i * 8 + j] = a;
        }
    }
}

__global__ __launch_bounds__(THREADS)
void dct_main_kernel(const float4* __restrict__ in4, float4* __restrict__ out4)
{
    __shared__ float4 sm[THREADS * STRIDE4];
    const int t = threadIdx.x;
    const size_t base = (size_t)blockIdx.x * (THREADS * 16);
    const int trow = t >> 4;   // which strip row this thread's coalesced slot maps to
    const int tcol = t & 15;

    // 1) coalesced gmem -> smem (each warp instr: 512B contiguous)
#pragma unroll
    for (int k = 0; k < 16; ++k)
        sm[(k * 8 + trow) * STRIDE4 + tcol] = in4[base + k * THREADS + t];
    __syncthreads();

    // 2) own strip: smem -> regs, transform, regs -> smem (conflict-free via pad)
    float x[64];
    float4* sp = &sm[t * STRIDE4];
#pragma unroll
    for (int k = 0; k < 16; ++k) {
        float4 v = sp[k];
        x[4 * k + 0] = v.x; x[4 * k + 1] = v.y;
        x[4 * k + 2] = v.z; x[4 * k + 3] = v.w;
    }
    dct64_inplace(x);
#pragma unroll
    for (int k = 0; k < 16; ++k)
        sp[k] = make_float4(x[4 * k + 0], x[4 * k + 1], x[4 * k + 2], x[4 * k + 3]);
    __syncthreads();

    // 3) coalesced smem -> gmem
#pragma unroll
    for (int k = 0; k < 16; ++k)
        out4[base + k * THREADS + t] = sm[(k * 8 + trow) * STRIDE4 + tcol];
}

// Tail path (strip count not divisible by THREADS): direct, uncoalesced but tiny.
__global__ void dct_tail_kernel(const float4* __restrict__ in4,
                                float4* __restrict__ out4,
                                int first_strip, int nstrips)
{
    int strip = first_strip + blockIdx.x * blockDim.x + threadIdx.x;
    if (strip >= nstrips) return;
    float x[64];
    const float4* ip = in4 + (size_t)strip * 16;
#pragma unroll
    for (int k = 0; k < 16; ++k) {
        float4 v = ip[k];
        x[4 * k + 0] = v.x; x[4 * k + 1] = v.y;
        x[4 * k + 2] = v.z; x[4 * k + 3] = v.w;
    }
    dct64_inplace(x);
    float4* op = out4 + (size_t)strip * 16;
#pragma unroll
    for (int k = 0; k < 16; ++k)
        op[k] = make_float4(x[4 * k + 0], x[4 * k + 1], x[4 * k + 2], x[4 * k + 3]);
}

extern "C" void kernel_launch(void* const* d_in, const int* in_sizes, int n_in,
                              void* d_out, int out_size)
{
    const float4* in4 = (const float4*)d_in[0];  // (8,3,1024,1024) fp32, contiguous
    float4* out4      = (float4*)d_out;

    int nstrips = in_sizes[0] / 64;              // 393216 for the bench shape
    int nfull   = nstrips / THREADS;             // full blocks of 128 strips
    if (nfull > 0)
        dct_main_kernel<<<nfull, THREADS>>>(in4, out4);
    int rem = nstrips - nfull * THREADS;
    if (rem > 0) {
        int first = nfull * THREADS;
        dct_tail_kernel<<<(rem + 127) / 128, 128>>>(in4, out4, first, nstrips);
    }
}